// round 3
// baseline (speedup 1.0000x reference)
#include <cuda_runtime.h>
#include <math_constants.h>

#define BB 2
#define HH 8
#define LL 2048
#define DD 64
#define CC 512
#define NQ 16
#define NK 32
#define BLKQ 128
#define BLKK 64

// ---------------- scratch (no allocations allowed) ----------------
__device__ float g_q[BB*HH*LL*DD];
__device__ float g_k[BB*HH*LL*DD];
__device__ float g_v[BB*HH*LL*DD];
__device__ float g_qm[BB*HH*NQ*DD];
__device__ float g_km[BB*HH*NK*DD];
__device__ float g_qsim[BB*HH*NQ];
__device__ float g_ksim[BB*HH*NK];
__device__ int   g_cnt[BB*HH*NQ];
__device__ int   g_list[BB*HH*NQ*NK];
__device__ float g_ot[BB*LL*CC];

// ---------------- QKV GEMM: x[4096,512] @ Wqkv[512,1536] + b, scatter to q/k/v [B,H,L,D] ----------------
__global__ void __launch_bounds__(256) gemm_qkv(const float* __restrict__ A,
                                                const float* __restrict__ W,
                                                const float* __restrict__ bias) {
    __shared__ float As[16][68];
    __shared__ float Bs[16][64];
    const int K = CC, N = 3 * CC;
    int tid = threadIdx.x;
    int tx = tid & 15, ty = tid >> 4;
    int m0 = blockIdx.y * 64, n0 = blockIdx.x * 64;
    float acc[4][4] = {};
    for (int k0 = 0; k0 < K; k0 += 16) {
        #pragma unroll
        for (int i = 0; i < 4; i++) {
            int idx = tid + i * 256;
            int mm = idx >> 4, kk = idx & 15;
            As[kk][mm] = A[(m0 + mm) * K + k0 + kk];
        }
        #pragma unroll
        for (int i = 0; i < 4; i++) {
            int idx = tid + i * 256;
            int kk = idx >> 6, nn = idx & 63;
            Bs[kk][nn] = W[(k0 + kk) * N + n0 + nn];
        }
        __syncthreads();
        #pragma unroll
        for (int kk = 0; kk < 16; kk++) {
            float4 av = *(const float4*)&As[kk][ty * 4];
            float4 bv = *(const float4*)&Bs[kk][tx * 4];
            acc[0][0] += av.x * bv.x; acc[0][1] += av.x * bv.y; acc[0][2] += av.x * bv.z; acc[0][3] += av.x * bv.w;
            acc[1][0] += av.y * bv.x; acc[1][1] += av.y * bv.y; acc[1][2] += av.y * bv.z; acc[1][3] += av.y * bv.w;
            acc[2][0] += av.z * bv.x; acc[2][1] += av.z * bv.y; acc[2][2] += av.z * bv.z; acc[2][3] += av.z * bv.w;
            acc[3][0] += av.w * bv.x; acc[3][1] += av.w * bv.y; acc[3][2] += av.w * bv.z; acc[3][3] += av.w * bv.w;
        }
        __syncthreads();
    }
    #pragma unroll
    for (int r = 0; r < 4; r++) {
        int m = m0 + ty * 4 + r;
        int b = m >> 11, l = m & 2047;
        #pragma unroll
        for (int c = 0; c < 4; c++) {
            int j = n0 + tx * 4 + c;
            float val = acc[r][c] + bias[j];
            int t = j >> 9;
            int h = (j >> 6) & 7;
            int d = j & 63;
            float* dst = (t == 0) ? g_q : (t == 1) ? g_k : g_v;
            dst[(((b * HH + h) * LL) + l) * DD + d] = val;
        }
    }
}

// ---------------- block means + min-cosine ----------------
template<int BLK, bool ISQ>
__global__ void __launch_bounds__(128) block_meta(int nb) {
    __shared__ float tile[BLK * 65];
    __shared__ float mean[64];
    __shared__ float red[128];
    __shared__ float nm_s;
    const float* t = ISQ ? g_q : g_k;
    float* mout = ISQ ? g_qm : g_km;
    float* simout = ISQ ? g_qsim : g_ksim;
    int blkid = blockIdx.x % nb;
    int bh = blockIdx.x / nb;
    const float* base = t + (bh * LL + blkid * BLK) * DD;
    int tid = threadIdx.x;
    for (int i = tid; i < BLK * DD; i += 128) {
        int r = i >> 6, d = i & 63;
        tile[r * 65 + d] = base[i];
    }
    __syncthreads();
    if (tid < 64) {
        float s = 0.f;
        for (int r = 0; r < BLK; r++) s += tile[r * 65 + tid];
        s *= (1.0f / BLK);
        mean[tid] = s;
        mout[blockIdx.x * 64 + tid] = s;
    }
    __syncthreads();
    if (tid == 0) {
        float s = 0.f;
        for (int d = 0; d < 64; d++) s += mean[d] * mean[d];
        nm_s = sqrtf(s) + 1e-6f;
    }
    __syncthreads();
    float mycos = CUDART_INF_F;
    if (tid < BLK) {
        float dot = 0.f, nr = 0.f;
        for (int d = 0; d < 64; d++) {
            float xv = tile[tid * 65 + d];
            dot += xv * mean[d];
            nr += xv * xv;
        }
        mycos = dot / ((sqrtf(nr) + 1e-6f) * nm_s);
    }
    red[tid] = mycos;
    __syncthreads();
    for (int s = 64; s > 0; s >>= 1) {
        if (tid < s) red[tid] = fminf(red[tid], red[tid + s]);
        __syncthreads();
    }
    if (tid == 0) simout[blockIdx.x] = red[0];
}

// ---------------- pooled softmax + CDF keep mask -> compacted kept-block lists ----------------
__global__ void __launch_bounds__(512) mask_kernel() {
    __shared__ float qm_s[NQ * DD];
    __shared__ float km_s[NK * DD];
    __shared__ float pooled[NQ][NK + 1];
    __shared__ float ksim_s[NK];
    int bh = blockIdx.x;
    int tid = threadIdx.x;
    for (int i = tid; i < NQ * DD; i += 512) qm_s[i] = g_qm[bh * NQ * DD + i];
    for (int i = tid; i < NK * DD; i += 512) km_s[i] = g_km[bh * NK * DD + i];
    if (tid < NK) ksim_s[tid] = g_ksim[bh * NK + tid];
    __syncthreads();
    {
        int qi = tid >> 5, j = tid & 31;
        const float* qv = &qm_s[qi * DD];
        const float* kv = &km_s[j * DD];
        float dot = 0.f;
        #pragma unroll
        for (int d = 0; d < DD; d++) dot += qv[d] * kv[d];
        pooled[qi][j] = dot * 0.125f;
    }
    __syncthreads();
    int w = tid >> 5;        // warp = Q row
    int lane = tid & 31;
    float v = pooled[w][lane];
    float mx = v;
    #pragma unroll
    for (int s = 16; s > 0; s >>= 1) mx = fmaxf(mx, __shfl_xor_sync(0xffffffffu, mx, s));
    float p = expf(v - mx);
    float sum = p;
    #pragma unroll
    for (int s = 16; s > 0; s >>= 1) sum += __shfl_xor_sync(0xffffffffu, sum, s);
    p /= sum;
    // bitonic sort descending (stable tie-break by ascending index)
    float sv = p;
    int si = lane;
    #pragma unroll
    for (int k = 2; k <= 32; k <<= 1) {
        #pragma unroll
        for (int j = k >> 1; j > 0; j >>= 1) {
            float ov = __shfl_xor_sync(0xffffffffu, sv, j);
            int   oi = __shfl_xor_sync(0xffffffffu, si, j);
            bool iprecede = (sv > ov) || (sv == ov && si < oi);
            bool lower = ((lane & j) == 0);
            bool dir = ((lane & k) == 0);
            bool keep_mine = ((lower == iprecede) == dir);
            if (!keep_mine) { sv = ov; si = oi; }
        }
    }
    float csum = sv;
    #pragma unroll
    for (int s = 1; s < 32; s <<= 1) {
        float t = __shfl_up_sync(0xffffffffu, csum, s);
        if (lane >= s) csum += t;
    }
    bool kept_sorted = (csum - sv) < 0.98f;
    unsigned keepmask = __reduce_or_sync(0xffffffffu, kept_sorted ? (1u << si) : 0u);
    bool qself = g_qsim[bh * NQ + w] > 0.6f;
    bool kself = ksim_s[lane] > 0.6f;
    bool fin = ((keepmask >> lane) & 1u) || !qself || !kself;
    unsigned fmask = __ballot_sync(0xffffffffu, fin);
    int pos = __popc(fmask & ((1u << lane) - 1u));
    int rowid = bh * NQ + w;
    if (fin) g_list[rowid * NK + pos] = lane;
    if (lane == 0) g_cnt[rowid] = __popc(fmask);
}

// ---------------- masked flash attention ----------------
// CTA = 64 Q rows (half of a 128-row Q block), 128 threads, 2 threads per row
// (each owns a 32-wide half of D). Grid: (NQ*2, B*H) = 512 CTAs -> ~5 CTAs/SM.
__global__ void __launch_bounds__(128) attn_kernel() {
    __shared__ float Ks[64 * 64];
    __shared__ float Vs[64 * 64];
    int bh = blockIdx.y;      // 0..15
    int qhb = blockIdx.x;     // 0..31 (half Q-block)
    int qb = qhb >> 1;
    int tid = threadIdx.x;    // 0..127
    int r = tid >> 1;         // 0..63 row within half-block
    int half = (tid & 1) * 32;
    int row = qhb * 64 + r;
    const float* qp = g_q + (bh * LL + row) * DD + half;
    float qreg[32];
    #pragma unroll
    for (int i = 0; i < 8; i++) {
        float4 v = *(const float4*)(qp + i * 4);
        qreg[4*i] = v.x; qreg[4*i+1] = v.y; qreg[4*i+2] = v.z; qreg[4*i+3] = v.w;
    }
    float m = -CUDART_INF_F, l = 0.f;
    float acc[32];
    #pragma unroll
    for (int d = 0; d < 32; d++) acc[d] = 0.f;
    int cnt = g_cnt[bh * NQ + qb];
    const int* __restrict__ list = g_list + (bh * NQ + qb) * NK;

    for (int it = 0; it < cnt; it++) {
        int kb = list[it];
        __syncthreads();
        const float4* Kg = (const float4*)(g_k + (bh * LL + kb * BLKK) * DD);
        const float4* Vg = (const float4*)(g_v + (bh * LL + kb * BLKK) * DD);
        #pragma unroll
        for (int i = 0; i < 8; i++) {
            ((float4*)Ks)[tid + i * 128] = Kg[tid + i * 128];
            ((float4*)Vs)[tid + i * 128] = Vg[tid + i * 128];
        }
        __syncthreads();
        for (int j = 0; j < 64; j += 2) {
            const float* k0 = &Ks[j * 64 + half];
            const float* k1 = &Ks[(j + 1) * 64 + half];
            float s0 = 0.f, s1 = 0.f;
            #pragma unroll
            for (int i = 0; i < 8; i++) {
                float4 a = *(const float4*)(k0 + 4 * i);
                float4 b = *(const float4*)(k1 + 4 * i);
                s0 += qreg[4*i]*a.x + qreg[4*i+1]*a.y + qreg[4*i+2]*a.z + qreg[4*i+3]*a.w;
                s1 += qreg[4*i]*b.x + qreg[4*i+1]*b.y + qreg[4*i+2]*b.z + qreg[4*i+3]*b.w;
            }
            s0 += __shfl_xor_sync(0xffffffffu, s0, 1);
            s1 += __shfl_xor_sync(0xffffffffu, s1, 1);
            s0 *= 0.125f; s1 *= 0.125f;
            float mn = fmaxf(m, fmaxf(s0, s1));
            if (mn > m) {
                float f = __expf(m - mn);
                l *= f;
                #pragma unroll
                for (int d = 0; d < 32; d++) acc[d] *= f;
                m = mn;
            }
            float p0 = __expf(s0 - m);
            float p1 = __expf(s1 - m);
            l += p0 + p1;
            const float* v0 = &Vs[j * 64 + half];
            const float* v1 = &Vs[(j + 1) * 64 + half];
            #pragma unroll
            for (int i = 0; i < 8; i++) {
                float4 a = *(const float4*)(v0 + 4 * i);
                float4 b = *(const float4*)(v1 + 4 * i);
                acc[4*i]   += p0 * a.x + p1 * b.x;
                acc[4*i+1] += p0 * a.y + p1 * b.y;
                acc[4*i+2] += p0 * a.z + p1 * b.z;
                acc[4*i+3] += p0 * a.w + p1 * b.w;
            }
        }
    }
    float inv = 1.0f / l;
    int b = bh >> 3, h = bh & 7;
    float* op = g_ot + (b * LL + row) * CC + h * DD + half;
    #pragma unroll
    for (int i = 0; i < 8; i++) {
        float4 v;
        v.x = acc[4*i] * inv; v.y = acc[4*i+1] * inv;
        v.z = acc[4*i+2] * inv; v.w = acc[4*i+3] * inv;
        *(float4*)(op + 4 * i) = v;
    }
}

// ---------------- output projection: ot[4096,512] @ Wproj[512,512] + b ----------------
__global__ void __launch_bounds__(256) gemm_proj(const float* __restrict__ W,
                                                 const float* __restrict__ bias,
                                                 float* __restrict__ out) {
    __shared__ float As[16][68];
    __shared__ float Bs[16][64];
    const int K = CC, N = CC;
    const float* __restrict__ A = g_ot;
    int tid = threadIdx.x;
    int tx = tid & 15, ty = tid >> 4;
    int m0 = blockIdx.y * 64, n0 = blockIdx.x * 64;
    float acc[4][4] = {};
    for (int k0 = 0; k0 < K; k0 += 16) {
        #pragma unroll
        for (int i = 0; i < 4; i++) {
            int idx = tid + i * 256;
            int mm = idx >> 4, kk = idx & 15;
            As[kk][mm] = A[(m0 + mm) * K + k0 + kk];
        }
        #pragma unroll
        for (int i = 0; i < 4; i++) {
            int idx = tid + i * 256;
            int kk = idx >> 6, nn = idx & 63;
            Bs[kk][nn] = W[(k0 + kk) * N + n0 + nn];
        }
        __syncthreads();
        #pragma unroll
        for (int kk = 0; kk < 16; kk++) {
            float4 av = *(const float4*)&As[kk][ty * 4];
            float4 bv = *(const float4*)&Bs[kk][tx * 4];
            acc[0][0] += av.x * bv.x; acc[0][1] += av.x * bv.y; acc[0][2] += av.x * bv.z; acc[0][3] += av.x * bv.w;
            acc[1][0] += av.y * bv.x; acc[1][1] += av.y * bv.y; acc[1][2] += av.y * bv.z; acc[1][3] += av.y * bv.w;
            acc[2][0] += av.z * bv.x; acc[2][1] += av.z * bv.y; acc[2][2] += av.z * bv.z; acc[2][3] += av.z * bv.w;
            acc[3][0] += av.w * bv.x; acc[3][1] += av.w * bv.y; acc[3][2] += av.w * bv.z; acc[3][3] += av.w * bv.w;
        }
        __syncthreads();
    }
    #pragma unroll
    for (int r = 0; r < 4; r++) {
        int m = m0 + ty * 4 + r;
        #pragma unroll
        for (int c = 0; c < 4; c++) {
            int j = n0 + tx * 4 + c;
            out[m * N + j] = acc[r][c] + bias[j];
        }
    }
}

extern "C" void kernel_launch(void* const* d_in, const int* in_sizes, int n_in,
                              void* d_out, int out_size) {
    const float* x     = (const float*)d_in[0];
    const float* Wqkv  = (const float*)d_in[1];
    const float* bqkv  = (const float*)d_in[2];
    const float* Wproj = (const float*)d_in[3];
    const float* bproj = (const float*)d_in[4];
    float* out = (float*)d_out;

    dim3 g1(24, 64);                       // N=1536/64, M=4096/64
    gemm_qkv<<<g1, 256>>>(x, Wqkv, bqkv);

    block_meta<BLKQ, true><<<BB * HH * NQ, 128>>>(NQ);
    block_meta<BLKK, false><<<BB * HH * NK, 128>>>(NK);

    mask_kernel<<<BB * HH, 512>>>();

    dim3 ga(NQ * 2, BB * HH);
    attn_kernel<<<ga, 128>>>();

    dim3 g2(8, 64);                        // N=512/64, M=4096/64
    gemm_proj<<<g2, 256>>>(Wproj, bproj, out);
}

// round 4
// speedup vs baseline: 2.8755x; 2.8755x over previous
#include <cuda_runtime.h>
#include <math_constants.h>

#define BB 2
#define HH 8
#define LL 2048
#define DD 64
#define CC 512
#define NQ 16
#define NK 32
#define BLKQ 128
#define BLKK 64

// ---------------- scratch (no allocations allowed) ----------------
__device__ float g_q[BB*HH*LL*DD];
__device__ float g_k[BB*HH*LL*DD];
__device__ float g_v[BB*HH*LL*DD];
__device__ float g_qm[BB*HH*NQ*DD];
__device__ float g_km[BB*HH*NK*DD];
__device__ float g_qsim[BB*HH*NQ];
__device__ float g_ksim[BB*HH*NK];
__device__ int   g_cnt[BB*HH*NQ];
__device__ int   g_list[BB*HH*NQ*NK];
__device__ float g_ot[BB*LL*CC];

__device__ __forceinline__ unsigned f2tf(float x) {
    unsigned r;
    asm("cvt.rna.tf32.f32 %0, %1;" : "=r"(r) : "f"(x));
    return r;
}
__device__ __forceinline__ float f2tff(float x) { return __uint_as_float(f2tf(x)); }

#define MMA_TF32(c, a0, a1, a2, a3, b0, b1)                                   \
    asm volatile(                                                             \
        "mma.sync.aligned.m16n8k8.row.col.f32.tf32.tf32.f32 "                 \
        "{%0,%1,%2,%3},{%4,%5,%6,%7},{%8,%9},{%0,%1,%2,%3};"                  \
        : "+f"((c)[0]), "+f"((c)[1]), "+f"((c)[2]), "+f"((c)[3])              \
        : "r"(a0), "r"(a1), "r"(a2), "r"(a3), "r"(b0), "r"(b1))

// ---------------- QKV GEMM: x[4096,512] @ Wqkv[512,1536] + b, scatter to q/k/v [B,H,L,D] ----------------
__global__ void __launch_bounds__(256) gemm_qkv(const float* __restrict__ A,
                                                const float* __restrict__ W,
                                                const float* __restrict__ bias) {
    __shared__ float As[16][68];
    __shared__ float Bs[16][64];
    const int K = CC, N = 3 * CC;
    int tid = threadIdx.x;
    int tx = tid & 15, ty = tid >> 4;
    int m0 = blockIdx.y * 64, n0 = blockIdx.x * 64;
    float acc[4][4] = {};
    for (int k0 = 0; k0 < K; k0 += 16) {
        #pragma unroll
        for (int i = 0; i < 4; i++) {
            int idx = tid + i * 256;
            int mm = idx >> 4, kk = idx & 15;
            As[kk][mm] = A[(m0 + mm) * K + k0 + kk];
        }
        #pragma unroll
        for (int i = 0; i < 4; i++) {
            int idx = tid + i * 256;
            int kk = idx >> 6, nn = idx & 63;
            Bs[kk][nn] = W[(k0 + kk) * N + n0 + nn];
        }
        __syncthreads();
        #pragma unroll
        for (int kk = 0; kk < 16; kk++) {
            float4 av = *(const float4*)&As[kk][ty * 4];
            float4 bv = *(const float4*)&Bs[kk][tx * 4];
            acc[0][0] += av.x * bv.x; acc[0][1] += av.x * bv.y; acc[0][2] += av.x * bv.z; acc[0][3] += av.x * bv.w;
            acc[1][0] += av.y * bv.x; acc[1][1] += av.y * bv.y; acc[1][2] += av.y * bv.z; acc[1][3] += av.y * bv.w;
            acc[2][0] += av.z * bv.x; acc[2][1] += av.z * bv.y; acc[2][2] += av.z * bv.z; acc[2][3] += av.z * bv.w;
            acc[3][0] += av.w * bv.x; acc[3][1] += av.w * bv.y; acc[3][2] += av.w * bv.z; acc[3][3] += av.w * bv.w;
        }
        __syncthreads();
    }
    #pragma unroll
    for (int r = 0; r < 4; r++) {
        int m = m0 + ty * 4 + r;
        int b = m >> 11, l = m & 2047;
        #pragma unroll
        for (int c = 0; c < 4; c++) {
            int j = n0 + tx * 4 + c;
            float val = acc[r][c] + bias[j];
            int t = j >> 9;
            int h = (j >> 6) & 7;
            int d = j & 63;
            float* dst = (t == 0) ? g_q : (t == 1) ? g_k : g_v;
            dst[(((b * HH + h) * LL) + l) * DD + d] = val;
        }
    }
}

// ---------------- block means + min-cosine ----------------
template<int BLK, bool ISQ>
__global__ void __launch_bounds__(128) block_meta(int nb) {
    __shared__ float tile[BLK * 65];
    __shared__ float mean[64];
    __shared__ float red[128];
    __shared__ float nm_s;
    const float* t = ISQ ? g_q : g_k;
    float* mout = ISQ ? g_qm : g_km;
    float* simout = ISQ ? g_qsim : g_ksim;
    int blkid = blockIdx.x % nb;
    int bh = blockIdx.x / nb;
    const float* base = t + (bh * LL + blkid * BLK) * DD;
    int tid = threadIdx.x;
    for (int i = tid; i < BLK * DD; i += 128) {
        int r = i >> 6, d = i & 63;
        tile[r * 65 + d] = base[i];
    }
    __syncthreads();
    if (tid < 64) {
        float s = 0.f;
        for (int r = 0; r < BLK; r++) s += tile[r * 65 + tid];
        s *= (1.0f / BLK);
        mean[tid] = s;
        mout[blockIdx.x * 64 + tid] = s;
    }
    __syncthreads();
    if (tid == 0) {
        float s = 0.f;
        for (int d = 0; d < 64; d++) s += mean[d] * mean[d];
        nm_s = sqrtf(s) + 1e-6f;
    }
    __syncthreads();
    float mycos = CUDART_INF_F;
    if (tid < BLK) {
        float dot = 0.f, nr = 0.f;
        for (int d = 0; d < 64; d++) {
            float xv = tile[tid * 65 + d];
            dot += xv * mean[d];
            nr += xv * xv;
        }
        mycos = dot / ((sqrtf(nr) + 1e-6f) * nm_s);
    }
    red[tid] = mycos;
    __syncthreads();
    for (int s = 64; s > 0; s >>= 1) {
        if (tid < s) red[tid] = fminf(red[tid], red[tid + s]);
        __syncthreads();
    }
    if (tid == 0) simout[blockIdx.x] = red[0];
}

// ---------------- pooled softmax + CDF keep mask -> compacted kept-block lists ----------------
__global__ void __launch_bounds__(512) mask_kernel() {
    __shared__ float qm_s[NQ * DD];
    __shared__ float km_s[NK * DD];
    __shared__ float pooled[NQ][NK + 1];
    __shared__ float ksim_s[NK];
    int bh = blockIdx.x;
    int tid = threadIdx.x;
    for (int i = tid; i < NQ * DD; i += 512) qm_s[i] = g_qm[bh * NQ * DD + i];
    for (int i = tid; i < NK * DD; i += 512) km_s[i] = g_km[bh * NK * DD + i];
    if (tid < NK) ksim_s[tid] = g_ksim[bh * NK + tid];
    __syncthreads();
    {
        int qi = tid >> 5, j = tid & 31;
        const float* qv = &qm_s[qi * DD];
        const float* kv = &km_s[j * DD];
        float dot = 0.f;
        #pragma unroll
        for (int d = 0; d < DD; d++) dot += qv[d] * kv[d];
        pooled[qi][j] = dot * 0.125f;
    }
    __syncthreads();
    int w = tid >> 5;
    int lane = tid & 31;
    float v = pooled[w][lane];
    float mx = v;
    #pragma unroll
    for (int s = 16; s > 0; s >>= 1) mx = fmaxf(mx, __shfl_xor_sync(0xffffffffu, mx, s));
    float p = expf(v - mx);
    float sum = p;
    #pragma unroll
    for (int s = 16; s > 0; s >>= 1) sum += __shfl_xor_sync(0xffffffffu, sum, s);
    p /= sum;
    float sv = p;
    int si = lane;
    #pragma unroll
    for (int k = 2; k <= 32; k <<= 1) {
        #pragma unroll
        for (int j = k >> 1; j > 0; j >>= 1) {
            float ov = __shfl_xor_sync(0xffffffffu, sv, j);
            int   oi = __shfl_xor_sync(0xffffffffu, si, j);
            bool iprecede = (sv > ov) || (sv == ov && si < oi);
            bool lower = ((lane & j) == 0);
            bool dir = ((lane & k) == 0);
            bool keep_mine = ((lower == iprecede) == dir);
            if (!keep_mine) { sv = ov; si = oi; }
        }
    }
    float csum = sv;
    #pragma unroll
    for (int s = 1; s < 32; s <<= 1) {
        float t = __shfl_up_sync(0xffffffffu, csum, s);
        if (lane >= s) csum += t;
    }
    bool kept_sorted = (csum - sv) < 0.98f;
    unsigned keepmask = __reduce_or_sync(0xffffffffu, kept_sorted ? (1u << si) : 0u);
    bool qself = g_qsim[bh * NQ + w] > 0.6f;
    bool kself = ksim_s[lane] > 0.6f;
    bool fin = ((keepmask >> lane) & 1u) || !qself || !kself;
    unsigned fmask = __ballot_sync(0xffffffffu, fin);
    int pos = __popc(fmask & ((1u << lane) - 1u));
    int rowid = bh * NQ + w;
    if (fin) g_list[rowid * NK + pos] = lane;
    if (lane == 0) g_cnt[rowid] = __popc(fmask);
}

// ---------------- tf32 tensor-core flash attention ----------------
// CTA: 64 Q rows of one (b,h); 4 warps, each owns a 16-row strip.
// Per kept 64-key block: S = Q K^T via m16n8k8 tf32 mma, online softmax in
// registers, P -> smem, O += P V via mma.
#define LDP 72
__global__ void __launch_bounds__(128) attn_kernel() {
    extern __shared__ float sm[];
    float* Ks = sm;                 // [64][LDP]
    float* Vs = sm + 64 * LDP;      // [64][LDP]
    float* Ps = sm + 128 * LDP;     // [64][LDP]

    int bh = blockIdx.y;       // 0..15
    int qt = blockIdx.x;       // 0..31 (64-row Q tile)
    int qb = qt >> 1;          // 128-row mask block
    int tid = threadIdx.x;
    int w = tid >> 5;          // warp 0..3
    int lane = tid & 31;
    int g = lane >> 2;         // 0..7
    int t = lane & 3;          // 0..3

    // Q fragments (rows w*16+g and +8), pre-scaled and tf32-rounded
    unsigned qa[8][4];
    {
        const float* q0 = g_q + (bh * LL + qt * 64 + w * 16 + g) * DD;
        const float* q1 = q0 + 8 * DD;
        #pragma unroll
        for (int kc = 0; kc < 8; kc++) {
            qa[kc][0] = f2tf(q0[kc * 8 + t] * 0.125f);
            qa[kc][1] = f2tf(q1[kc * 8 + t] * 0.125f);
            qa[kc][2] = f2tf(q0[kc * 8 + t + 4] * 0.125f);
            qa[kc][3] = f2tf(q1[kc * 8 + t + 4] * 0.125f);
        }
    }

    float oacc[8][4];
    #pragma unroll
    for (int dt = 0; dt < 8; dt++) { oacc[dt][0]=0.f; oacc[dt][1]=0.f; oacc[dt][2]=0.f; oacc[dt][3]=0.f; }
    float m0 = -CUDART_INF_F, m1 = -CUDART_INF_F;
    float l0 = 0.f, l1 = 0.f;

    int cnt = g_cnt[bh * NQ + qb];
    const int* __restrict__ list = g_list + (bh * NQ + qb) * NK;

    for (int it = 0; it < cnt; it++) {
        int kb = list[it];
        __syncthreads();
        // load K/V block (64x64) into smem, converted to tf32 values
        {
            const float4* Kg = (const float4*)(g_k + (bh * LL + kb * BLKK) * DD);
            const float4* Vg = (const float4*)(g_v + (bh * LL + kb * BLKK) * DD);
            #pragma unroll
            for (int i = 0; i < 8; i++) {
                int idx = tid + i * 128;         // 0..1023 float4 chunks
                int row = idx >> 4, c4 = idx & 15;
                float4 kv = Kg[idx];
                float4 vv = Vg[idx];
                float* kd = &Ks[row * LDP + c4 * 4];
                kd[0] = f2tff(kv.x); kd[1] = f2tff(kv.y); kd[2] = f2tff(kv.z); kd[3] = f2tff(kv.w);
                float* vd = &Vs[row * LDP + c4 * 4];
                vd[0] = f2tff(vv.x); vd[1] = f2tff(vv.y); vd[2] = f2tff(vv.z); vd[3] = f2tff(vv.w);
            }
        }
        __syncthreads();

        // S = Q K^T  (strip 16 x 64)
        float sc[8][4];
        #pragma unroll
        for (int nt = 0; nt < 8; nt++) { sc[nt][0]=0.f; sc[nt][1]=0.f; sc[nt][2]=0.f; sc[nt][3]=0.f; }
        #pragma unroll
        for (int kc = 0; kc < 8; kc++) {
            #pragma unroll
            for (int nt = 0; nt < 8; nt++) {
                unsigned b0 = __float_as_uint(Ks[(nt * 8 + g) * LDP + kc * 8 + t]);
                unsigned b1 = __float_as_uint(Ks[(nt * 8 + g) * LDP + kc * 8 + t + 4]);
                MMA_TF32(sc[nt], qa[kc][0], qa[kc][1], qa[kc][2], qa[kc][3], b0, b1);
            }
        }

        // online softmax over the 64 keys of this block
        float mx0 = -CUDART_INF_F, mx1 = -CUDART_INF_F;
        #pragma unroll
        for (int nt = 0; nt < 8; nt++) {
            mx0 = fmaxf(mx0, fmaxf(sc[nt][0], sc[nt][1]));
            mx1 = fmaxf(mx1, fmaxf(sc[nt][2], sc[nt][3]));
        }
        mx0 = fmaxf(mx0, __shfl_xor_sync(0xffffffffu, mx0, 1));
        mx0 = fmaxf(mx0, __shfl_xor_sync(0xffffffffu, mx0, 2));
        mx1 = fmaxf(mx1, __shfl_xor_sync(0xffffffffu, mx1, 1));
        mx1 = fmaxf(mx1, __shfl_xor_sync(0xffffffffu, mx1, 2));
        float nm0 = fmaxf(m0, mx0);
        float nm1 = fmaxf(m1, mx1);
        float f0 = __expf(m0 - nm0);
        float f1 = __expf(m1 - nm1);
        #pragma unroll
        for (int dt = 0; dt < 8; dt++) {
            oacc[dt][0] *= f0; oacc[dt][1] *= f0;
            oacc[dt][2] *= f1; oacc[dt][3] *= f1;
        }
        l0 *= f0; l1 *= f1;
        m0 = nm0; m1 = nm1;

        float s0 = 0.f, s1 = 0.f;
        float* p0 = &Ps[(w * 16 + g) * LDP];
        float* p1 = &Ps[(w * 16 + g + 8) * LDP];
        #pragma unroll
        for (int nt = 0; nt < 8; nt++) {
            float e00 = __expf(sc[nt][0] - nm0);
            float e01 = __expf(sc[nt][1] - nm0);
            float e10 = __expf(sc[nt][2] - nm1);
            float e11 = __expf(sc[nt][3] - nm1);
            s0 += e00 + e01; s1 += e10 + e11;
            *(float2*)&p0[nt * 8 + 2 * t] = make_float2(f2tff(e00), f2tff(e01));
            *(float2*)&p1[nt * 8 + 2 * t] = make_float2(f2tff(e10), f2tff(e11));
        }
        s0 += __shfl_xor_sync(0xffffffffu, s0, 1);
        s0 += __shfl_xor_sync(0xffffffffu, s0, 2);
        s1 += __shfl_xor_sync(0xffffffffu, s1, 1);
        s1 += __shfl_xor_sync(0xffffffffu, s1, 2);
        l0 += s0; l1 += s1;
        __syncwarp();

        // O += P V
        #pragma unroll
        for (int kc = 0; kc < 8; kc++) {
            unsigned a0 = __float_as_uint(Ps[(w * 16 + g) * LDP + kc * 8 + t]);
            unsigned a1 = __float_as_uint(Ps[(w * 16 + g + 8) * LDP + kc * 8 + t]);
            unsigned a2 = __float_as_uint(Ps[(w * 16 + g) * LDP + kc * 8 + t + 4]);
            unsigned a3 = __float_as_uint(Ps[(w * 16 + g + 8) * LDP + kc * 8 + t + 4]);
            #pragma unroll
            for (int dt = 0; dt < 8; dt++) {
                unsigned b0 = __float_as_uint(Vs[(kc * 8 + t) * LDP + dt * 8 + g]);
                unsigned b1 = __float_as_uint(Vs[(kc * 8 + t + 4) * LDP + dt * 8 + g]);
                MMA_TF32(oacc[dt], a0, a1, a2, a3, b0, b1);
            }
        }
        __syncwarp();
    }

    float inv0 = 1.0f / l0;
    float inv1 = 1.0f / l1;
    int b = bh >> 3, h = bh & 7;
    int grow = qt * 64 + w * 16 + g;
    float* o0 = g_ot + (b * LL + grow) * CC + h * DD;
    float* o1 = o0 + 8 * CC;
    #pragma unroll
    for (int dt = 0; dt < 8; dt++) {
        *(float2*)&o0[dt * 8 + 2 * t] = make_float2(oacc[dt][0] * inv0, oacc[dt][1] * inv0);
        *(float2*)&o1[dt * 8 + 2 * t] = make_float2(oacc[dt][2] * inv1, oacc[dt][3] * inv1);
    }
}

// ---------------- output projection: ot[4096,512] @ Wproj[512,512] + b ----------------
__global__ void __launch_bounds__(256) gemm_proj(const float* __restrict__ W,
                                                 const float* __restrict__ bias,
                                                 float* __restrict__ out) {
    __shared__ float As[16][68];
    __shared__ float Bs[16][64];
    const int K = CC, N = CC;
    const float* __restrict__ A = g_ot;
    int tid = threadIdx.x;
    int tx = tid & 15, ty = tid >> 4;
    int m0 = blockIdx.y * 64, n0 = blockIdx.x * 64;
    float acc[4][4] = {};
    for (int k0 = 0; k0 < K; k0 += 16) {
        #pragma unroll
        for (int i = 0; i < 4; i++) {
            int idx = tid + i * 256;
            int mm = idx >> 4, kk = idx & 15;
            As[kk][mm] = A[(m0 + mm) * K + k0 + kk];
        }
        #pragma unroll
        for (int i = 0; i < 4; i++) {
            int idx = tid + i * 256;
            int kk = idx >> 6, nn = idx & 63;
            Bs[kk][nn] = W[(k0 + kk) * N + n0 + nn];
        }
        __syncthreads();
        #pragma unroll
        for (int kk = 0; kk < 16; kk++) {
            float4 av = *(const float4*)&As[kk][ty * 4];
            float4 bv = *(const float4*)&Bs[kk][tx * 4];
            acc[0][0] += av.x * bv.x; acc[0][1] += av.x * bv.y; acc[0][2] += av.x * bv.z; acc[0][3] += av.x * bv.w;
            acc[1][0] += av.y * bv.x; acc[1][1] += av.y * bv.y; acc[1][2] += av.y * bv.z; acc[1][3] += av.y * bv.w;
            acc[2][0] += av.z * bv.x; acc[2][1] += av.z * bv.y; acc[2][2] += av.z * bv.z; acc[2][3] += av.z * bv.w;
            acc[3][0] += av.w * bv.x; acc[3][1] += av.w * bv.y; acc[3][2] += av.w * bv.z; acc[3][3] += av.w * bv.w;
        }
        __syncthreads();
    }
    #pragma unroll
    for (int r = 0; r < 4; r++) {
        int m = m0 + ty * 4 + r;
        #pragma unroll
        for (int c = 0; c < 4; c++) {
            int j = n0 + tx * 4 + c;
            out[m * N + j] = acc[r][c] + bias[j];
        }
    }
}

extern "C" void kernel_launch(void* const* d_in, const int* in_sizes, int n_in,
                              void* d_out, int out_size) {
    const float* x     = (const float*)d_in[0];
    const float* Wqkv  = (const float*)d_in[1];
    const float* bqkv  = (const float*)d_in[2];
    const float* Wproj = (const float*)d_in[3];
    const float* bproj = (const float*)d_in[4];
    float* out = (float*)d_out;

    dim3 g1(24, 64);
    gemm_qkv<<<g1, 256>>>(x, Wqkv, bqkv);

    block_meta<BLKQ, true><<<BB * HH * NQ, 128>>>(NQ);
    block_meta<BLKK, false><<<BB * HH * NK, 128>>>(NK);

    mask_kernel<<<BB * HH, 512>>>();

    const int smem = 192 * LDP * sizeof(float);   // Ks+Vs+Ps = 55296 B
    cudaFuncSetAttribute(attn_kernel, cudaFuncAttributeMaxDynamicSharedMemorySize, smem);
    dim3 ga(32, BB * HH);
    attn_kernel<<<ga, 128, smem>>>();

    dim3 g2(8, 64);
    gemm_proj<<<g2, 256>>>(Wproj, bproj, out);
}

// round 6
// speedup vs baseline: 3.5778x; 1.2442x over previous
#include <cuda_runtime.h>
#include <math_constants.h>

#define BB 2
#define HH 8
#define LL 2048
#define DD 64
#define CC 512
#define NQ 16
#define NK 32
#define BLKQ 128
#define BLKK 64

// ---------------- scratch (no allocations allowed) ----------------
__device__ float g_q[BB*HH*LL*DD];
__device__ float g_k[BB*HH*LL*DD];
__device__ float g_v[BB*HH*LL*DD];
__device__ float g_qm[BB*HH*NQ*DD];
__device__ float g_km[BB*HH*NK*DD];
__device__ float g_qsim[BB*HH*NQ];
__device__ float g_ksim[BB*HH*NK];
__device__ int   g_cnt[BB*HH*NQ];
__device__ int   g_list[BB*HH*NQ*NK];
__device__ float g_ot[BB*LL*CC];

__device__ __forceinline__ unsigned f2tf(float x) {
    unsigned r;
    asm("cvt.rna.tf32.f32 %0, %1;" : "=r"(r) : "f"(x));
    return r;
}
__device__ __forceinline__ float f2tff(float x) { return __uint_as_float(f2tf(x)); }

#define MMA_TF32(c, a0, a1, a2, a3, b0, b1)                                   \
    asm volatile(                                                             \
        "mma.sync.aligned.m16n8k8.row.col.f32.tf32.tf32.f32 "                 \
        "{%0,%1,%2,%3},{%4,%5,%6,%7},{%8,%9},{%0,%1,%2,%3};"                  \
        : "+f"((c)[0]), "+f"((c)[1]), "+f"((c)[2]), "+f"((c)[3])              \
        : "r"(a0), "r"(a1), "r"(a2), "r"(a3), "r"(b0), "r"(b1))

// ---------------- 3xTF32 tensor-core GEMM (near-fp32 accuracy) ----------------
// CTA 64x64 tile, 128 threads (4 warps, each a 32x32 quadrant), k-chunk 32.
// hi/lo split: a*b ~= ah*bh + ah*bl + al*bh  (residual ~2^-21 relative).
// QKV=true: A comes from the x input, epilogue scatters to g_q/g_k/g_v.
// QKV=false: A is the internal g_ot buffer (resolved INSIDE the kernel -- a
// __device__ symbol must never be passed from host code), writes to out.
template<int N, bool QKV>
__global__ void __launch_bounds__(128) gemm_tf32(const float* __restrict__ Ain,
                                                 const float* __restrict__ W,
                                                 const float* __restrict__ bias,
                                                 float* __restrict__ out) {
    __shared__ float Ah[64][36], Al[64][36];
    __shared__ float Bh[32][72], Bl[32][72];
    const float* __restrict__ A = QKV ? Ain : (const float*)g_ot;
    const int K = CC;
    int tid = threadIdx.x;
    int w = tid >> 5, lane = tid & 31;
    int g = lane >> 2, t = lane & 3;
    int wm = (w & 1) * 32, wn = (w >> 1) * 32;
    int m0 = blockIdx.y * 64, n0 = blockIdx.x * 64;

    float acc[2][4][4] = {};

    for (int k0 = 0; k0 < K; k0 += 32) {
        __syncthreads();
        #pragma unroll
        for (int i = 0; i < 4; i++) {
            int lin = tid + i * 128;            // 0..511 float4
            int row = lin >> 3, c4 = (lin & 7) * 4;
            float4 v = *(const float4*)&A[(m0 + row) * K + k0 + c4];
            float h0 = f2tff(v.x), h1 = f2tff(v.y), h2 = f2tff(v.z), h3 = f2tff(v.w);
            Ah[row][c4+0] = h0; Ah[row][c4+1] = h1; Ah[row][c4+2] = h2; Ah[row][c4+3] = h3;
            Al[row][c4+0] = f2tff(v.x - h0); Al[row][c4+1] = f2tff(v.y - h1);
            Al[row][c4+2] = f2tff(v.z - h2); Al[row][c4+3] = f2tff(v.w - h3);
        }
        #pragma unroll
        for (int i = 0; i < 4; i++) {
            int lin = tid + i * 128;
            int row = lin >> 4, c4 = (lin & 15) * 4;
            float4 v = *(const float4*)&W[(k0 + row) * N + n0 + c4];
            float h0 = f2tff(v.x), h1 = f2tff(v.y), h2 = f2tff(v.z), h3 = f2tff(v.w);
            Bh[row][c4+0] = h0; Bh[row][c4+1] = h1; Bh[row][c4+2] = h2; Bh[row][c4+3] = h3;
            Bl[row][c4+0] = f2tff(v.x - h0); Bl[row][c4+1] = f2tff(v.y - h1);
            Bl[row][c4+2] = f2tff(v.z - h2); Bl[row][c4+3] = f2tff(v.w - h3);
        }
        __syncthreads();
        #pragma unroll
        for (int kc = 0; kc < 4; kc++) {
            unsigned ah[2][4], al[2][4];
            #pragma unroll
            for (int mf = 0; mf < 2; mf++) {
                int r0 = wm + mf * 16 + g;
                ah[mf][0] = __float_as_uint(Ah[r0][kc*8+t]);
                ah[mf][1] = __float_as_uint(Ah[r0+8][kc*8+t]);
                ah[mf][2] = __float_as_uint(Ah[r0][kc*8+t+4]);
                ah[mf][3] = __float_as_uint(Ah[r0+8][kc*8+t+4]);
                al[mf][0] = __float_as_uint(Al[r0][kc*8+t]);
                al[mf][1] = __float_as_uint(Al[r0+8][kc*8+t]);
                al[mf][2] = __float_as_uint(Al[r0][kc*8+t+4]);
                al[mf][3] = __float_as_uint(Al[r0+8][kc*8+t+4]);
            }
            #pragma unroll
            for (int nt = 0; nt < 4; nt++) {
                int nc = wn + nt * 8 + g;
                unsigned bh0 = __float_as_uint(Bh[kc*8+t][nc]);
                unsigned bh1 = __float_as_uint(Bh[kc*8+t+4][nc]);
                unsigned bl0 = __float_as_uint(Bl[kc*8+t][nc]);
                unsigned bl1 = __float_as_uint(Bl[kc*8+t+4][nc]);
                #pragma unroll
                for (int mf = 0; mf < 2; mf++) {
                    MMA_TF32(acc[mf][nt], ah[mf][0], ah[mf][1], ah[mf][2], ah[mf][3], bh0, bh1);
                    MMA_TF32(acc[mf][nt], ah[mf][0], ah[mf][1], ah[mf][2], ah[mf][3], bl0, bl1);
                    MMA_TF32(acc[mf][nt], al[mf][0], al[mf][1], al[mf][2], al[mf][3], bh0, bh1);
                }
            }
        }
    }

    // epilogue
    #pragma unroll
    for (int mf = 0; mf < 2; mf++) {
        #pragma unroll
        for (int rr = 0; rr < 2; rr++) {
            int m = m0 + wm + mf * 16 + g + rr * 8;
            #pragma unroll
            for (int nt = 0; nt < 4; nt++) {
                #pragma unroll
                for (int cc = 0; cc < 2; cc++) {
                    int j = n0 + wn + nt * 8 + 2 * t + cc;
                    float val = acc[mf][nt][rr * 2 + cc] + bias[j];
                    if (QKV) {
                        int b = m >> 11, l = m & 2047;
                        int ty = j >> 9, h = (j >> 6) & 7, d = j & 63;
                        float* dst = (ty == 0) ? g_q : (ty == 1) ? g_k : g_v;
                        dst[(((b * HH + h) * LL) + l) * DD + d] = val;
                    } else {
                        out[m * N + j] = val;
                    }
                }
            }
        }
    }
}

// ---------------- block means + min-cosine ----------------
template<int BLK, bool ISQ>
__global__ void __launch_bounds__(128) block_meta(int nb) {
    __shared__ float tile[BLK * 65];
    __shared__ float mean[64];
    __shared__ float red[128];
    __shared__ float nm_s;
    const float* t = ISQ ? g_q : g_k;
    float* mout = ISQ ? g_qm : g_km;
    float* simout = ISQ ? g_qsim : g_ksim;
    int blkid = blockIdx.x % nb;
    int bh = blockIdx.x / nb;
    const float* base = t + (bh * LL + blkid * BLK) * DD;
    int tid = threadIdx.x;
    for (int i = tid; i < BLK * DD; i += 128) {
        int r = i >> 6, d = i & 63;
        tile[r * 65 + d] = base[i];
    }
    __syncthreads();
    if (tid < 64) {
        float s = 0.f;
        for (int r = 0; r < BLK; r++) s += tile[r * 65 + tid];
        s *= (1.0f / BLK);
        mean[tid] = s;
        mout[blockIdx.x * 64 + tid] = s;
    }
    __syncthreads();
    if (tid == 0) {
        float s = 0.f;
        for (int d = 0; d < 64; d++) s += mean[d] * mean[d];
        nm_s = sqrtf(s) + 1e-6f;
    }
    __syncthreads();
    float mycos = CUDART_INF_F;
    if (tid < BLK) {
        float dot = 0.f, nr = 0.f;
        for (int d = 0; d < 64; d++) {
            float xv = tile[tid * 65 + d];
            dot += xv * mean[d];
            nr += xv * xv;
        }
        mycos = dot / ((sqrtf(nr) + 1e-6f) * nm_s);
    }
    red[tid] = mycos;
    __syncthreads();
    for (int s = 64; s > 0; s >>= 1) {
        if (tid < s) red[tid] = fminf(red[tid], red[tid + s]);
        __syncthreads();
    }
    if (tid == 0) simout[blockIdx.x] = red[0];
}

// ---------------- pooled softmax + CDF keep mask -> compacted kept-block lists ----------------
__global__ void __launch_bounds__(512) mask_kernel() {
    __shared__ float qm_s[NQ * DD];
    __shared__ float km_s[NK * DD];
    __shared__ float pooled[NQ][NK + 1];
    __shared__ float ksim_s[NK];
    int bh = blockIdx.x;
    int tid = threadIdx.x;
    for (int i = tid; i < NQ * DD; i += 512) qm_s[i] = g_qm[bh * NQ * DD + i];
    for (int i = tid; i < NK * DD; i += 512) km_s[i] = g_km[bh * NK * DD + i];
    if (tid < NK) ksim_s[tid] = g_ksim[bh * NK + tid];
    __syncthreads();
    {
        int qi = tid >> 5, j = tid & 31;
        const float* qv = &qm_s[qi * DD];
        const float* kv = &km_s[j * DD];
        float dot = 0.f;
        #pragma unroll
        for (int d = 0; d < DD; d++) dot += qv[d] * kv[d];
        pooled[qi][j] = dot * 0.125f;
    }
    __syncthreads();
    int w = tid >> 5;
    int lane = tid & 31;
    float v = pooled[w][lane];
    float mx = v;
    #pragma unroll
    for (int s = 16; s > 0; s >>= 1) mx = fmaxf(mx, __shfl_xor_sync(0xffffffffu, mx, s));
    float p = expf(v - mx);
    float sum = p;
    #pragma unroll
    for (int s = 16; s > 0; s >>= 1) sum += __shfl_xor_sync(0xffffffffu, sum, s);
    p /= sum;
    float sv = p;
    int si = lane;
    #pragma unroll
    for (int k = 2; k <= 32; k <<= 1) {
        #pragma unroll
        for (int j = k >> 1; j > 0; j >>= 1) {
            float ov = __shfl_xor_sync(0xffffffffu, sv, j);
            int   oi = __shfl_xor_sync(0xffffffffu, si, j);
            bool iprecede = (sv > ov) || (sv == ov && si < oi);
            bool lower = ((lane & j) == 0);
            bool dir = ((lane & k) == 0);
            bool keep_mine = ((lower == iprecede) == dir);
            if (!keep_mine) { sv = ov; si = oi; }
        }
    }
    float csum = sv;
    #pragma unroll
    for (int s = 1; s < 32; s <<= 1) {
        float t = __shfl_up_sync(0xffffffffu, csum, s);
        if (lane >= s) csum += t;
    }
    bool kept_sorted = (csum - sv) < 0.98f;
    unsigned keepmask = __reduce_or_sync(0xffffffffu, kept_sorted ? (1u << si) : 0u);
    bool qself = g_qsim[bh * NQ + w] > 0.6f;
    bool kself = ksim_s[lane] > 0.6f;
    bool fin = ((keepmask >> lane) & 1u) || !qself || !kself;
    unsigned fmask = __ballot_sync(0xffffffffu, fin);
    int pos = __popc(fmask & ((1u << lane) - 1u));
    int rowid = bh * NQ + w;
    if (fin) g_list[rowid * NK + pos] = lane;
    if (lane == 0) g_cnt[rowid] = __popc(fmask);
}

// ---------------- tf32 tensor-core flash attention ----------------
#define LDP 72
__global__ void __launch_bounds__(128) attn_kernel() {
    extern __shared__ float sm[];
    float* Ks = sm;                 // [64][LDP]
    float* Vs = sm + 64 * LDP;      // [64][LDP]
    float* Ps = sm + 128 * LDP;     // [64][LDP]

    int bh = blockIdx.y;
    int qt = blockIdx.x;
    int qb = qt >> 1;
    int tid = threadIdx.x;
    int w = tid >> 5;
    int lane = tid & 31;
    int g = lane >> 2;
    int t = lane & 3;

    unsigned qa[8][4];
    {
        const float* q0 = g_q + (bh * LL + qt * 64 + w * 16 + g) * DD;
        const float* q1 = q0 + 8 * DD;
        #pragma unroll
        for (int kc = 0; kc < 8; kc++) {
            qa[kc][0] = f2tf(q0[kc * 8 + t] * 0.125f);
            qa[kc][1] = f2tf(q1[kc * 8 + t] * 0.125f);
            qa[kc][2] = f2tf(q0[kc * 8 + t + 4] * 0.125f);
            qa[kc][3] = f2tf(q1[kc * 8 + t + 4] * 0.125f);
        }
    }

    float oacc[8][4];
    #pragma unroll
    for (int dt = 0; dt < 8; dt++) { oacc[dt][0]=0.f; oacc[dt][1]=0.f; oacc[dt][2]=0.f; oacc[dt][3]=0.f; }
    float m0 = -CUDART_INF_F, m1 = -CUDART_INF_F;
    float l0 = 0.f, l1 = 0.f;

    int cnt = g_cnt[bh * NQ + qb];
    const int* __restrict__ list = g_list + (bh * NQ + qb) * NK;

    for (int it = 0; it < cnt; it++) {
        int kb = list[it];
        __syncthreads();
        {
            const float4* Kg = (const float4*)(g_k + (bh * LL + kb * BLKK) * DD);
            const float4* Vg = (const float4*)(g_v + (bh * LL + kb * BLKK) * DD);
            #pragma unroll
            for (int i = 0; i < 8; i++) {
                int idx = tid + i * 128;
                int row = idx >> 4, c4 = idx & 15;
                float4 kv = Kg[idx];
                float4 vv = Vg[idx];
                float* kd = &Ks[row * LDP + c4 * 4];
                kd[0] = f2tff(kv.x); kd[1] = f2tff(kv.y); kd[2] = f2tff(kv.z); kd[3] = f2tff(kv.w);
                float* vd = &Vs[row * LDP + c4 * 4];
                vd[0] = f2tff(vv.x); vd[1] = f2tff(vv.y); vd[2] = f2tff(vv.z); vd[3] = f2tff(vv.w);
            }
        }
        __syncthreads();

        float sc[8][4];
        #pragma unroll
        for (int nt = 0; nt < 8; nt++) { sc[nt][0]=0.f; sc[nt][1]=0.f; sc[nt][2]=0.f; sc[nt][3]=0.f; }
        #pragma unroll
        for (int kc = 0; kc < 8; kc++) {
            #pragma unroll
            for (int nt = 0; nt < 8; nt++) {
                unsigned b0 = __float_as_uint(Ks[(nt * 8 + g) * LDP + kc * 8 + t]);
                unsigned b1 = __float_as_uint(Ks[(nt * 8 + g) * LDP + kc * 8 + t + 4]);
                MMA_TF32(sc[nt], qa[kc][0], qa[kc][1], qa[kc][2], qa[kc][3], b0, b1);
            }
        }

        float mx0 = -CUDART_INF_F, mx1 = -CUDART_INF_F;
        #pragma unroll
        for (int nt = 0; nt < 8; nt++) {
            mx0 = fmaxf(mx0, fmaxf(sc[nt][0], sc[nt][1]));
            mx1 = fmaxf(mx1, fmaxf(sc[nt][2], sc[nt][3]));
        }
        mx0 = fmaxf(mx0, __shfl_xor_sync(0xffffffffu, mx0, 1));
        mx0 = fmaxf(mx0, __shfl_xor_sync(0xffffffffu, mx0, 2));
        mx1 = fmaxf(mx1, __shfl_xor_sync(0xffffffffu, mx1, 1));
        mx1 = fmaxf(mx1, __shfl_xor_sync(0xffffffffu, mx1, 2));
        float nm0 = fmaxf(m0, mx0);
        float nm1 = fmaxf(m1, mx1);
        float f0 = __expf(m0 - nm0);
        float f1 = __expf(m1 - nm1);
        #pragma unroll
        for (int dt = 0; dt < 8; dt++) {
            oacc[dt][0] *= f0; oacc[dt][1] *= f0;
            oacc[dt][2] *= f1; oacc[dt][3] *= f1;
        }
        l0 *= f0; l1 *= f1;
        m0 = nm0; m1 = nm1;

        float s0 = 0.f, s1 = 0.f;
        float* p0 = &Ps[(w * 16 + g) * LDP];
        float* p1 = &Ps[(w * 16 + g + 8) * LDP];
        #pragma unroll
        for (int nt = 0; nt < 8; nt++) {
            float e00 = __expf(sc[nt][0] - nm0);
            float e01 = __expf(sc[nt][1] - nm0);
            float e10 = __expf(sc[nt][2] - nm1);
            float e11 = __expf(sc[nt][3] - nm1);
            s0 += e00 + e01; s1 += e10 + e11;
            *(float2*)&p0[nt * 8 + 2 * t] = make_float2(f2tff(e00), f2tff(e01));
            *(float2*)&p1[nt * 8 + 2 * t] = make_float2(f2tff(e10), f2tff(e11));
        }
        s0 += __shfl_xor_sync(0xffffffffu, s0, 1);
        s0 += __shfl_xor_sync(0xffffffffu, s0, 2);
        s1 += __shfl_xor_sync(0xffffffffu, s1, 1);
        s1 += __shfl_xor_sync(0xffffffffu, s1, 2);
        l0 += s0; l1 += s1;
        __syncwarp();

        #pragma unroll
        for (int kc = 0; kc < 8; kc++) {
            unsigned a0 = __float_as_uint(Ps[(w * 16 + g) * LDP + kc * 8 + t]);
            unsigned a1 = __float_as_uint(Ps[(w * 16 + g + 8) * LDP + kc * 8 + t]);
            unsigned a2 = __float_as_uint(Ps[(w * 16 + g) * LDP + kc * 8 + t + 4]);
            unsigned a3 = __float_as_uint(Ps[(w * 16 + g + 8) * LDP + kc * 8 + t + 4]);
            #pragma unroll
            for (int dt = 0; dt < 8; dt++) {
                unsigned b0 = __float_as_uint(Vs[(kc * 8 + t) * LDP + dt * 8 + g]);
                unsigned b1 = __float_as_uint(Vs[(kc * 8 + t + 4) * LDP + dt * 8 + g]);
                MMA_TF32(oacc[dt], a0, a1, a2, a3, b0, b1);
            }
        }
        __syncwarp();
    }

    float inv0 = 1.0f / l0;
    float inv1 = 1.0f / l1;
    int b = bh >> 3, h = bh & 7;
    int grow = qt * 64 + w * 16 + g;
    float* o0 = g_ot + (b * LL + grow) * CC + h * DD;
    float* o1 = o0 + 8 * CC;
    #pragma unroll
    for (int dt = 0; dt < 8; dt++) {
        *(float2*)&o0[dt * 8 + 2 * t] = make_float2(oacc[dt][0] * inv0, oacc[dt][1] * inv0);
        *(float2*)&o1[dt * 8 + 2 * t] = make_float2(oacc[dt][2] * inv1, oacc[dt][3] * inv1);
    }
}

extern "C" void kernel_launch(void* const* d_in, const int* in_sizes, int n_in,
                              void* d_out, int out_size) {
    const float* x     = (const float*)d_in[0];
    const float* Wqkv  = (const float*)d_in[1];
    const float* bqkv  = (const float*)d_in[2];
    const float* Wproj = (const float*)d_in[3];
    const float* bproj = (const float*)d_in[4];
    float* out = (float*)d_out;

    dim3 g1(24, 64);                       // N=1536/64, M=4096/64
    gemm_tf32<3 * CC, true><<<g1, 128>>>(x, Wqkv, bqkv, nullptr);

    block_meta<BLKQ, true><<<BB * HH * NQ, 128>>>(NQ);
    block_meta<BLKK, false><<<BB * HH * NK, 128>>>(NK);

    mask_kernel<<<BB * HH, 512>>>();

    const int smem = 192 * LDP * sizeof(float);
    cudaFuncSetAttribute(attn_kernel, cudaFuncAttributeMaxDynamicSharedMemorySize, smem);
    dim3 ga(32, BB * HH);
    attn_kernel<<<ga, 128, smem>>>();

    dim3 g2(8, 64);                        // N=512/64, M=4096/64
    gemm_tf32<CC, false><<<g2, 128>>>(nullptr, Wproj, bproj, out);
}